// round 2
// baseline (speedup 1.0000x reference)
#include <cuda_runtime.h>
#include <math.h>

#define BB 2
#define SS 2048
#define DIM 2048
#define NH 16
#define KVH 8
#define HD 128

// scratch (device globals — no allocation allowed)
__device__ float g_q[BB * SS * NH * HD];    // [B*S, NH, HD]
__device__ float g_k[BB * SS * KVH * HD];   // [B*S, KVH, HD]
__device__ float g_v[BB * SS * KVH * HD];   // [B*S, KVH, HD]
__device__ float g_att[BB * SS * NH * HD];  // [B*S, NH, HD]
__device__ float g_cos[SS * 64];
__device__ float g_sin[SS * 64];

// ---------------------------------------------------------------------------
// RoPE tables (fp64 for accuracy; tiny kernel, rerun every launch — deterministic)
// ---------------------------------------------------------------------------
__global__ void rope_table_kernel() {
    int idx = blockIdx.x * blockDim.x + threadIdx.x;
    if (idx >= SS * 64) return;
    int i = idx & 63;
    int s = idx >> 6;
    double inv = pow(10000.0, -(double)i / 64.0);
    double ang = (double)s * inv;
    g_cos[idx] = (float)cos(ang);
    g_sin[idx] = (float)sin(ang);
}

// ---------------------------------------------------------------------------
// RoPE apply for q and k in one grid.
// First BB*SS*NH*64 items -> g_q (NH heads); rest -> g_k (KVH heads).
// out[i]    = x[i]*c - x[i+64]*s ; out[i+64] = x[i+64]*c + x[i]*s
// ---------------------------------------------------------------------------
__global__ void rope_apply_kernel() {
    int idx = blockIdx.x * blockDim.x + threadIdx.x;
    const int qtotal = BB * SS * NH * 64;
    const int ktotal = BB * SS * KVH * 64;
    if (idx >= qtotal + ktotal) return;
    float* buf;
    int nheads;
    if (idx < qtotal) { buf = g_q; nheads = NH; }
    else { buf = g_k; nheads = KVH; idx -= qtotal; }
    int i = idx & 63;
    int h = (idx >> 6) % nheads;
    int rs = idx / (64 * nheads);
    int s = rs & (SS - 1);
    float c = g_cos[s * 64 + i];
    float sn = g_sin[s * 64 + i];
    float* p = buf + ((size_t)rs * nheads + h) * HD;
    float x0 = p[i];
    float x1 = p[i + 64];
    p[i] = x0 * c - x1 * sn;
    p[i + 64] = x1 * c + x0 * sn;
}

// ---------------------------------------------------------------------------
// Classic fp32 SGEMM: C[M,N] = A[M,K] @ W[K,N], all row-major.
// 128x128 block tile, BK=8, 256 threads, 8x8 per thread.
// M,N multiples of 128; K multiple of 8.
// ---------------------------------------------------------------------------
__device__ __forceinline__ void sgemm_body(
    const float* __restrict__ A, const float* __restrict__ W,
    float* __restrict__ C, int M, int N, int K, int bx, int by)
{
    __shared__ float As[8][128];  // transposed A tile: As[k][m]
    __shared__ float Bs[8][128];  // Bs[k][n]

    int tid = threadIdx.x;
    int row0 = by * 128;
    int col0 = bx * 128;

    int arow = tid >> 1;            // 0..127
    int acol = (tid & 1) * 4;       // 0 or 4
    int brow = tid >> 5;            // 0..7
    int bcol = (tid & 31) * 4;      // 0..124

    int tx = tid & 15;              // 0..15
    int ty = tid >> 4;              // 0..15

    float acc[8][8];
#pragma unroll
    for (int i = 0; i < 8; i++)
#pragma unroll
        for (int j = 0; j < 8; j++) acc[i][j] = 0.f;

    for (int kt = 0; kt < K; kt += 8) {
        float4 av = *(const float4*)(A + (size_t)(row0 + arow) * K + kt + acol);
        As[acol + 0][arow] = av.x;
        As[acol + 1][arow] = av.y;
        As[acol + 2][arow] = av.z;
        As[acol + 3][arow] = av.w;
        float4 bv = *(const float4*)(W + (size_t)(kt + brow) * N + col0 + bcol);
        *(float4*)&Bs[brow][bcol] = bv;
        __syncthreads();

#pragma unroll
        for (int k = 0; k < 8; k++) {
            float ra[8], rb[8];
            *(float4*)(&ra[0]) = *(float4*)&As[k][ty * 8];
            *(float4*)(&ra[4]) = *(float4*)&As[k][ty * 8 + 4];
            *(float4*)(&rb[0]) = *(float4*)&Bs[k][tx * 8];
            *(float4*)(&rb[4]) = *(float4*)&Bs[k][tx * 8 + 4];
#pragma unroll
            for (int i = 0; i < 8; i++)
#pragma unroll
                for (int j = 0; j < 8; j++)
                    acc[i][j] += ra[i] * rb[j];
        }
        __syncthreads();
    }

#pragma unroll
    for (int i = 0; i < 8; i++) {
#pragma unroll
        for (int j = 0; j < 8; j += 4) {
            float4 v = make_float4(acc[i][j], acc[i][j + 1], acc[i][j + 2], acc[i][j + 3]);
            *(float4*)(C + (size_t)(row0 + ty * 8 + i) * N + col0 + tx * 8 + j) = v;
        }
    }
}

__global__ __launch_bounds__(256) void sgemm_kernel(
    const float* __restrict__ A, const float* __restrict__ W,
    float* __restrict__ C, int M, int N, int K)
{
    sgemm_body(A, W, C, M, N, K, blockIdx.x, blockIdx.y);
}

// Fused K+V projection: grid.x = 2*(KVN/128); lower half -> Wk/g_k, upper -> Wv/g_v.
__global__ __launch_bounds__(256) void sgemm_kv_kernel(
    const float* __restrict__ A, const float* __restrict__ Wk,
    const float* __restrict__ Wv, int M, int K)
{
    const int NT = (KVH * HD) / 128;  // 8 column tiles
    int bx = blockIdx.x;
    if (bx < NT) sgemm_body(A, Wk, g_k, M, KVH * HD, K, bx, blockIdx.y);
    else         sgemm_body(A, Wv, g_v, M, KVH * HD, K, bx - NT, blockIdx.y);
}

// ---------------------------------------------------------------------------
// Causal GQA flash attention, fp32.
// Grid: (S/64, NH, B). Block: 128 threads.
// Thread t: row r = t&63 of the 64-query tile, half = t>>6.
//   half 0 scores keys [0,32), owns o dims [0,64)
//   half 1 scores keys [32,64), owns o dims [64,128)
// Online softmax state (m,l) replicated in the pair via SMEM reductions.
// ---------------------------------------------------------------------------
#define QS_STRIDE 132   // 128 + 4, keeps float4 alignment, conflict-free
#define SS_STRIDE 65

__global__ __launch_bounds__(128) void attn_kernel() {
    extern __shared__ float sm[];
    float* Qs = sm;                        // 64 * 132
    float* Ks = Qs + 64 * QS_STRIDE;       // 64 * 128
    float* Vs = Ks + 64 * 128;             // 64 * 128
    float* Sp = Vs + 64 * 128;             // 64 * 65 (probabilities)
    float* redM = Sp + 64 * SS_STRIDE;     // 2 * 64
    float* redS = redM + 128;              // 2 * 64

    int qt = blockIdx.x;
    int h = blockIdx.y;
    int b = blockIdx.z;
    int hk = h >> 1;  // rep = NH/KVH = 2
    int tid = threadIdx.x;
    int r = tid & 63;
    int half = tid >> 6;
    const float scale = 0.08838834764831845f;  // 1/sqrt(128)

    // load Q tile: rows qt*64..+63, strided layout [B*S, NH, HD]
    for (int i = tid; i < 64 * 32; i += 128) {
        int row = i >> 5;
        int col = (i & 31) << 2;
        float4 v = *(const float4*)(g_q + ((size_t)(b * SS + qt * 64 + row) * NH + h) * HD + col);
        *(float4*)&Qs[row * QS_STRIDE + col] = v;
    }

    float o[64];
#pragma unroll
    for (int d = 0; d < 64; d++) o[d] = 0.f;
    float m = -1e30f, l = 0.f;
    int qi = qt * 64 + r;

    for (int jt = 0; jt <= qt; jt++) {
        __syncthreads();  // prev iter done with Ks/Vs/Sp
        for (int i = tid; i < 64 * 32; i += 128) {
            int row = i >> 5;
            int col = (i & 31) << 2;
            size_t base = ((size_t)(b * SS + jt * 64 + row) * KVH + hk) * HD + col;
            *(float4*)&Ks[row * 128 + col] = *(const float4*)(g_k + base);
            *(float4*)&Vs[row * 128 + col] = *(const float4*)(g_v + base);
        }
        __syncthreads();

        // ---- scores for this thread's 32 keys ----
        float sreg[32];
#pragma unroll
        for (int jj = 0; jj < 32; jj++) sreg[jj] = 0.f;
        for (int k = 0; k < 128; k += 4) {
            float4 qv = *(float4*)&Qs[r * QS_STRIDE + k];
#pragma unroll
            for (int jj = 0; jj < 32; jj++) {
                float4 kv = *(float4*)&Ks[(half * 32 + jj) * 128 + k];
                sreg[jj] += qv.x * kv.x + qv.y * kv.y + qv.z * kv.z + qv.w * kv.w;
            }
        }

        float mloc = -1e30f;
        int kbase = jt * 64 + half * 32;
#pragma unroll
        for (int jj = 0; jj < 32; jj++) {
            float sv = sreg[jj] * scale;
            sv = (kbase + jj <= qi) ? sv : -1e30f;
            sreg[jj] = sv;
            mloc = fmaxf(mloc, sv);
        }
        redM[half * 64 + r] = mloc;
        __syncthreads();
        float mtile = fmaxf(redM[r], redM[64 + r]);
        float mnew = fmaxf(m, mtile);
        float alpha = __expf(m - mnew);
        float lsum = 0.f;
#pragma unroll
        for (int jj = 0; jj < 32; jj++) {
            float p = __expf(sreg[jj] - mnew);
            lsum += p;
            Sp[r * SS_STRIDE + half * 32 + jj] = p;
        }
        redS[half * 64 + r] = lsum;
#pragma unroll
        for (int d = 0; d < 64; d++) o[d] *= alpha;
        __syncthreads();
        l = l * alpha + redS[r] + redS[64 + r];
        m = mnew;

        // ---- o += P @ V over this thread's D half ----
        for (int j = 0; j < 64; j++) {
            float p = Sp[r * SS_STRIDE + j];
#pragma unroll
            for (int d = 0; d < 64; d += 4) {
                float4 vv = *(float4*)&Vs[j * 128 + half * 64 + d];
                o[d]     += p * vv.x;
                o[d + 1] += p * vv.y;
                o[d + 2] += p * vv.z;
                o[d + 3] += p * vv.w;
            }
        }
    }

    float inv = 1.f / l;
    size_t obase = ((size_t)(b * SS + qi) * NH + h) * HD + half * 64;
#pragma unroll
    for (int d = 0; d < 64; d += 4) {
        float4 v = make_float4(o[d] * inv, o[d + 1] * inv, o[d + 2] * inv, o[d + 3] * inv);
        *(float4*)(g_att + obase + d) = v;
    }
}

// ---------------------------------------------------------------------------

static const int ATTN_SMEM =
    (64 * QS_STRIDE + 64 * 128 * 2 + 64 * SS_STRIDE + 256) * (int)sizeof(float);

extern "C" void kernel_launch(void* const* d_in, const int* in_sizes, int n_in,
                              void* d_out, int out_size) {
    const float* x  = (const float*)d_in[0];   // [B,S,DIM]
    const float* Wq = (const float*)d_in[1];   // [DIM, NH*HD]
    const float* Wk = (const float*)d_in[2];   // [DIM, KVH*HD]
    const float* Wv = (const float*)d_in[3];   // [DIM, KVH*HD]
    const float* Wo = (const float*)d_in[4];   // [NH*HD, DIM]
    float* out = (float*)d_out;

    float *q, *att;
    cudaGetSymbolAddress((void**)&q, g_q);
    cudaGetSymbolAddress((void**)&att, g_att);

    cudaFuncSetAttribute(attn_kernel, cudaFuncAttributeMaxDynamicSharedMemorySize, ATTN_SMEM);

    const int M = BB * SS;  // 4096

    // projections
    sgemm_kernel<<<dim3((NH * HD) / 128, M / 128), 256>>>(x, Wq, q, M, NH * HD, DIM);
    sgemm_kv_kernel<<<dim3(2 * (KVH * HD) / 128, M / 128), 256>>>(x, Wk, Wv, M, DIM);

    // RoPE
    rope_table_kernel<<<(SS * 64 + 255) / 256, 256>>>();
    rope_apply_kernel<<<(BB * SS * (NH + KVH) * 64 + 255) / 256, 256>>>();

    // attention
    attn_kernel<<<dim3(SS / 64, NH, BB), 128, ATTN_SMEM>>>();

    // output projection
    sgemm_kernel<<<dim3(DIM / 128, M / 128), 256>>>(att, Wo, out, M, DIM, DIM);
}

// round 4
// speedup vs baseline: 1.3833x; 1.3833x over previous
#include <cuda_runtime.h>
#include <cuda_bf16.h>
#include <math.h>
#include <cstdint>

#define BB 2
#define SS 2048
#define DIM 2048
#define NH 16
#define KVH 8
#define HD 128
#define MM (BB * SS)          // 4096 rows
#define QKV_N 4096            // q(2048) | k(1024) | v(1024)
#define K3 6144               // 3 * 2048 split-K

// ---------------------------------------------------------------------------
// scratch (device globals — no allocation allowed)
// ---------------------------------------------------------------------------
__device__ __nv_bfloat16 g_xs[MM * K3];       // split x   [M, 3K]
__device__ __nv_bfloat16 g_atts[MM * K3];     // split att [M, 3K]
__device__ __nv_bfloat16 g_wt[QKV_N * K3];    // Wqkv^T split [4096, 3K]
__device__ __nv_bfloat16 g_wot[DIM * K3];     // Wo^T split   [2048, 3K]
__device__ float g_qkv[MM * QKV_N];           // [M, 4096] = q|k|v
__device__ float g_att[MM * DIM];             // [M, 2048]
__device__ float g_cos[SS * 64];
__device__ float g_sin[SS * 64];

__device__ __forceinline__ uint32_t smem_to_u32(const void* p) {
    uint32_t a;
    asm("{ .reg .u64 t; cvta.to.shared.u64 t, %1; cvt.u32.u64 %0, t; }" : "=r"(a) : "l"(p));
    return a;
}

// ---------------------------------------------------------------------------
// split A [4096, 2048] fp32 -> [4096, 6144] bf16: cols [0,2K)=hi, [2K,4K)=hi, [4K,6K)=lo
// ---------------------------------------------------------------------------
__global__ __launch_bounds__(256) void split_a_kernel(const float* __restrict__ A,
                                                      __nv_bfloat16* __restrict__ As) {
    int idx = blockIdx.x * 256 + threadIdx.x;
    if (idx >= MM * DIM) return;
    int m = idx >> 11, k = idx & 2047;
    float v = A[idx];
    __nv_bfloat16 h = __float2bfloat16(v);
    __nv_bfloat16 lo = __float2bfloat16(v - __bfloat162float(h));
    size_t rb = (size_t)m * K3 + k;
    As[rb] = h; As[rb + 2048] = h; As[rb + 4096] = lo;
}

// ---------------------------------------------------------------------------
// transpose+split W [2048, N] fp32 -> Wt [N, 6144] bf16: [0,2K)=hi, [2K,4K)=lo, [4K,6K)=hi
// ---------------------------------------------------------------------------
__global__ __launch_bounds__(256) void transpose_split_kernel(const float* __restrict__ W,
                                                              __nv_bfloat16* __restrict__ Wt, int N) {
    __shared__ float tile[32][33];
    int k0 = blockIdx.y * 32, n0 = blockIdx.x * 32;
    int tx = threadIdx.x, ty = threadIdx.y;
#pragma unroll
    for (int i = 0; i < 4; i++)
        tile[ty + i * 8][tx] = W[(size_t)(k0 + ty + i * 8) * N + n0 + tx];
    __syncthreads();
#pragma unroll
    for (int i = 0; i < 4; i++) {
        int n = n0 + ty + i * 8;
        float v = tile[tx][ty + i * 8];
        __nv_bfloat16 h = __float2bfloat16(v);
        __nv_bfloat16 lo = __float2bfloat16(v - __bfloat162float(h));
        size_t rb = (size_t)n * K3 + k0 + tx;
        Wt[rb] = h; Wt[rb + 2048] = lo; Wt[rb + 4096] = h;
    }
}

// ---------------------------------------------------------------------------
// bf16 mma.sync GEMM: C[M, Ntot] = A[M, K3] · Bt[Ntot, K3]^T
// CTA 128x128, BK=32, 3-stage cp.async, 8 warps (2x4), warp tile 64x32.
// Smem rows padded to 80B (stride 40 bf16) -> conflict-free ldmatrix.
// ---------------------------------------------------------------------------
#define NSTAGES 3
#define STAGE_ELEMS (128 * 40)                 // per operand per stage
#define GEMM_SMEM (NSTAGES * 2 * STAGE_ELEMS * 2)  // bytes = 61440
#define NKT (K3 / 32)                          // 192

__global__ __launch_bounds__(256) void gemm_kernel(const __nv_bfloat16* __restrict__ A,
                                                   const __nv_bfloat16* __restrict__ Bt,
                                                   float* __restrict__ C, int Ntot) {
    extern __shared__ __nv_bfloat16 smem[];
    int tid = threadIdx.x;
    int lane = tid & 31;
    int wid = tid >> 5;
    int wm = wid >> 2;        // 0..1
    int wn = wid & 3;         // 0..3

    size_t arow0 = (size_t)blockIdx.y * 128;
    size_t brow0 = (size_t)blockIdx.x * 128;
    const __nv_bfloat16* Ag = A + arow0 * K3;
    const __nv_bfloat16* Bg = Bt + brow0 * K3;

    uint32_t sbase = smem_to_u32(smem);
    const uint32_t boff = NSTAGES * STAGE_ELEMS * 2;  // byte offset of B region

    // cp.async stage loader: 512 x 16B per operand, 256 threads -> 2 each
    int lrow = tid >> 2;          // 0..63  (plus +64 on second pass)
    int lch = tid & 3;            // 0..3
    auto load_stage = [&](int kt, int s) {
        uint32_t abase = sbase + s * STAGE_ELEMS * 2;
        uint32_t bbase = sbase + boff + s * STAGE_ELEMS * 2;
        const __nv_bfloat16* ag = Ag + (size_t)kt * 32;
        const __nv_bfloat16* bg = Bg + (size_t)kt * 32;
#pragma unroll
        for (int i = 0; i < 2; i++) {
            int row = lrow + i * 64;
            uint32_t so = row * 80 + lch * 16;
            const void* pa = ag + (size_t)row * K3 + lch * 8;
            asm volatile("cp.async.cg.shared.global [%0], [%1], 16;" :: "r"(abase + so), "l"(pa));
            const void* pb = bg + (size_t)row * K3 + lch * 8;
            asm volatile("cp.async.cg.shared.global [%0], [%1], 16;" :: "r"(bbase + so), "l"(pb));
        }
        asm volatile("cp.async.commit_group;" ::: "memory");
    };

    float acc[4][4][4];
#pragma unroll
    for (int i = 0; i < 4; i++)
#pragma unroll
        for (int j = 0; j < 4; j++)
#pragma unroll
            for (int c = 0; c < 4; c++) acc[i][j][c] = 0.f;

    load_stage(0, 0);
    load_stage(1, 1);

    for (int kt = 0; kt < NKT; kt++) {
        int s = kt % NSTAGES;
        asm volatile("cp.async.wait_group 1;" ::: "memory");
        __syncthreads();

        uint32_t abase = sbase + s * STAGE_ELEMS * 2;
        uint32_t bbase = sbase + boff + s * STAGE_ELEMS * 2;
#pragma unroll
        for (int kk = 0; kk < 2; kk++) {
            uint32_t afr[4][4];
            uint32_t bfr[4][2];
#pragma unroll
            for (int mt = 0; mt < 4; mt++) {
                int row = wm * 64 + mt * 16 + (lane & 15);
                uint32_t addr = abase + row * 80 + kk * 32 + (lane >> 4) * 16;
                asm volatile("ldmatrix.sync.aligned.m8n8.x4.shared.b16 {%0,%1,%2,%3}, [%4];"
                             : "=r"(afr[mt][0]), "=r"(afr[mt][1]), "=r"(afr[mt][2]), "=r"(afr[mt][3])
                             : "r"(addr));
            }
#pragma unroll
            for (int nt = 0; nt < 4; nt++) {
                int nrow = wn * 32 + nt * 8 + (lane & 7);
                uint32_t addr = bbase + nrow * 80 + kk * 32 + ((lane >> 3) & 1) * 16;
                asm volatile("ldmatrix.sync.aligned.m8n8.x2.shared.b16 {%0,%1}, [%2];"
                             : "=r"(bfr[nt][0]), "=r"(bfr[nt][1]) : "r"(addr));
            }
#pragma unroll
            for (int mt = 0; mt < 4; mt++)
#pragma unroll
                for (int nt = 0; nt < 4; nt++) {
                    asm volatile(
                        "mma.sync.aligned.m16n8k16.row.col.f32.bf16.bf16.f32 "
                        "{%0,%1,%2,%3}, {%4,%5,%6,%7}, {%8,%9}, {%0,%1,%2,%3};"
                        : "+f"(acc[mt][nt][0]), "+f"(acc[mt][nt][1]),
                          "+f"(acc[mt][nt][2]), "+f"(acc[mt][nt][3])
                        : "r"(afr[mt][0]), "r"(afr[mt][1]), "r"(afr[mt][2]), "r"(afr[mt][3]),
                          "r"(bfr[nt][0]), "r"(bfr[nt][1]));
                }
        }
        __syncthreads();
        if (kt + 2 < NKT) load_stage(kt + 2, (kt + 2) % NSTAGES);
        else asm volatile("cp.async.commit_group;" ::: "memory");
    }

    // epilogue
    int r0 = lane >> 2;
    int c0 = (lane & 3) * 2;
#pragma unroll
    for (int mt = 0; mt < 4; mt++) {
        size_t m = arow0 + wm * 64 + mt * 16 + r0;
#pragma unroll
        for (int nt = 0; nt < 4; nt++) {
            size_t n = brow0 + wn * 32 + nt * 8 + c0;
            float2 v0 = make_float2(acc[mt][nt][0], acc[mt][nt][1]);
            float2 v1 = make_float2(acc[mt][nt][2], acc[mt][nt][3]);
            *(float2*)(C + m * Ntot + n) = v0;
            *(float2*)(C + (m + 8) * Ntot + n) = v1;
        }
    }
}

// ---------------------------------------------------------------------------
// RoPE tables (fp64 for accuracy)
// ---------------------------------------------------------------------------
__global__ void rope_table_kernel() {
    int idx = blockIdx.x * blockDim.x + threadIdx.x;
    if (idx >= SS * 64) return;
    int i = idx & 63;
    int s = idx >> 6;
    double inv = pow(10000.0, -(double)i / 64.0);
    double ang = (double)s * inv;
    g_cos[idx] = (float)cos(ang);
    g_sin[idx] = (float)sin(ang);
}

// RoPE apply in place on g_qkv: q cols [0,2048) (NH heads), k cols [2048,3072) (KVH heads)
__global__ void rope_apply_kernel() {
    int idx = blockIdx.x * blockDim.x + threadIdx.x;
    const int qtotal = MM * NH * 64;
    const int ktotal = MM * KVH * 64;
    if (idx >= qtotal + ktotal) return;
    int coloff, nheads;
    if (idx < qtotal) { coloff = 0; nheads = NH; }
    else { coloff = 2048; nheads = KVH; idx -= qtotal; }
    int i = idx & 63;
    int h = (idx >> 6) % nheads;
    int rs = idx / (64 * nheads);
    int s = rs & (SS - 1);
    float c = g_cos[s * 64 + i];
    float sn = g_sin[s * 64 + i];
    float* p = g_qkv + (size_t)rs * QKV_N + coloff + h * HD;
    float x0 = p[i];
    float x1 = p[i + 64];
    p[i] = x0 * c - x1 * sn;
    p[i + 64] = x1 * c + x0 * sn;
}

// ---------------------------------------------------------------------------
// Causal GQA flash attention, fp32 (R2-passing logic; strides into g_qkv).
// ---------------------------------------------------------------------------
#define QS_STRIDE 132
#define SS_STRIDE 65

__global__ __launch_bounds__(128) void attn_kernel() {
    extern __shared__ float sm[];
    float* Qs = sm;                        // 64 * 132
    float* Ks = Qs + 64 * QS_STRIDE;       // 64 * 128
    float* Vs = Ks + 64 * 128;             // 64 * 128
    float* Sp = Vs + 64 * 128;             // 64 * 65
    float* redM = Sp + 64 * SS_STRIDE;     // 128
    float* redS = redM + 128;              // 128

    int qt = blockIdx.x;
    int h = blockIdx.y;
    int b = blockIdx.z;
    int hk = h >> 1;
    int tid = threadIdx.x;
    int r = tid & 63;
    int half = tid >> 6;
    const float scale = 0.08838834764831845f;

    for (int i = tid; i < 64 * 32; i += 128) {
        int row = i >> 5;
        int col = (i & 31) << 2;
        float4 v = *(const float4*)(g_qkv + (size_t)(b * SS + qt * 64 + row) * QKV_N + h * HD + col);
        *(float4*)&Qs[row * QS_STRIDE + col] = v;
    }

    float o[64];
#pragma unroll
    for (int d = 0; d < 64; d++) o[d] = 0.f;
    float m = -1e30f, l = 0.f;
    int qi = qt * 64 + r;

    for (int jt = 0; jt <= qt; jt++) {
        __syncthreads();
        for (int i = tid; i < 64 * 32; i += 128) {
            int row = i >> 5;
            int col = (i & 31) << 2;
            size_t base = (size_t)(b * SS + jt * 64 + row) * QKV_N + hk * HD + col;
            *(float4*)&Ks[row * 128 + col] = *(const float4*)(g_qkv + base + 2048);
            *(float4*)&Vs[row * 128 + col] = *(const float4*)(g_qkv + base + 3072);
        }
        __syncthreads();

        float sreg[32];
#pragma unroll
        for (int jj = 0; jj < 32; jj++) sreg[jj] = 0.f;
        for (int k = 0; k < 128; k += 4) {
            float4 qv = *(float4*)&Qs[r * QS_STRIDE + k];
#pragma unroll
            for (int jj = 0; jj < 32; jj++) {
                float4 kv = *(float4*)&Ks[(half * 32 + jj) * 128 + k];
                sreg[jj] += qv.x * kv.x + qv.y * kv.y + qv.z * kv.z + qv.w * kv.w;
            }
        }

        float mloc = -1e30f;
        int kbase = jt * 64 + half * 32;
#pragma unroll
        for (int jj = 0; jj < 32; jj++) {
            float sv = sreg[jj] * scale;
            sv = (kbase + jj <= qi) ? sv : -1e30f;
            sreg[jj] = sv;
            mloc = fmaxf(mloc, sv);
        }
        redM[half * 64 + r] = mloc;
        __syncthreads();
        float mtile = fmaxf(redM[r], redM[64 + r]);
        float mnew = fmaxf(m, mtile);
        float alpha = __expf(m - mnew);
        float lsum = 0.f;
#pragma unroll
        for (int jj = 0; jj < 32; jj++) {
            float p = __expf(sreg[jj] - mnew);
            lsum += p;
            Sp[r * SS_STRIDE + half * 32 + jj] = p;
        }
        redS[half * 64 + r] = lsum;
#pragma unroll
        for (int d = 0; d < 64; d++) o[d] *= alpha;
        __syncthreads();
        l = l * alpha + redS[r] + redS[64 + r];
        m = mnew;

        for (int j = 0; j < 64; j++) {
            float p = Sp[r * SS_STRIDE + j];
#pragma unroll
            for (int d = 0; d < 64; d += 4) {
                float4 vv = *(float4*)&Vs[j * 128 + half * 64 + d];
                o[d]     += p * vv.x;
                o[d + 1] += p * vv.y;
                o[d + 2] += p * vv.z;
                o[d + 3] += p * vv.w;
            }
        }
    }

    float inv = 1.f / l;
    size_t obase = (size_t)(b * SS + qi) * DIM + h * HD + half * 64;
#pragma unroll
    for (int d = 0; d < 64; d += 4) {
        float4 v = make_float4(o[d] * inv, o[d + 1] * inv, o[d + 2] * inv, o[d + 3] * inv);
        *(float4*)(g_att + obase + d) = v;
    }
}

// ---------------------------------------------------------------------------

static const int ATTN_SMEM =
    (64 * QS_STRIDE + 64 * 128 * 2 + 64 * SS_STRIDE + 256) * (int)sizeof(float);

extern "C" void kernel_launch(void* const* d_in, const int* in_sizes, int n_in,
                              void* d_out, int out_size) {
    const float* x  = (const float*)d_in[0];   // [B,S,DIM]
    const float* Wq = (const float*)d_in[1];   // [DIM, 2048]
    const float* Wk = (const float*)d_in[2];   // [DIM, 1024]
    const float* Wv = (const float*)d_in[3];   // [DIM, 1024]
    const float* Wo = (const float*)d_in[4];   // [2048, DIM]
    float* out = (float*)d_out;

    __nv_bfloat16 *xs, *atts, *wt, *wot;
    float *qkv, *att;
    cudaGetSymbolAddress((void**)&xs, g_xs);
    cudaGetSymbolAddress((void**)&atts, g_atts);
    cudaGetSymbolAddress((void**)&wt, g_wt);
    cudaGetSymbolAddress((void**)&wot, g_wot);
    cudaGetSymbolAddress((void**)&qkv, g_qkv);
    cudaGetSymbolAddress((void**)&att, g_att);

    cudaFuncSetAttribute(attn_kernel, cudaFuncAttributeMaxDynamicSharedMemorySize, ATTN_SMEM);
    cudaFuncSetAttribute(gemm_kernel, cudaFuncAttributeMaxDynamicSharedMemorySize, GEMM_SMEM);

    // split inputs / weights (bf16 hi/lo; W transposed to K-major)
    split_a_kernel<<<(MM * DIM) / 256, 256>>>(x, xs);
    transpose_split_kernel<<<dim3(2048 / 32, 64), dim3(32, 8)>>>(Wq, wt, 2048);
    transpose_split_kernel<<<dim3(1024 / 32, 64), dim3(32, 8)>>>(Wk, wt + (size_t)2048 * K3, 1024);
    transpose_split_kernel<<<dim3(1024 / 32, 64), dim3(32, 8)>>>(Wv, wt + (size_t)3072 * K3, 1024);
    transpose_split_kernel<<<dim3(2048 / 32, 64), dim3(32, 8)>>>(Wo, wot, 2048);

    // fused QKV projection on tensor cores (mma.sync)
    gemm_kernel<<<dim3(QKV_N / 128, MM / 128), 256, GEMM_SMEM>>>(xs, wt, qkv, QKV_N);

    // RoPE
    rope_table_kernel<<<(SS * 64 + 255) / 256, 256>>>();
    rope_apply_kernel<<<(MM * (NH + KVH) * 64 + 255) / 256, 256>>>();

    // attention
    attn_kernel<<<dim3(SS / 64, NH, BB), 128, ATTN_SMEM>>>();

    // output projection on tensor cores
    split_a_kernel<<<(MM * DIM) / 256, 256>>>(att, atts);
    gemm_kernel<<<dim3(DIM / 128, MM / 128), 256, GEMM_SMEM>>>(atts, wot, out, DIM);
}

// round 7
// speedup vs baseline: 3.4583x; 2.5000x over previous
#include <cuda_runtime.h>
#include <cuda_bf16.h>
#include <math.h>
#include <cstdint>

#define BB 2
#define SS 2048
#define DIM 2048
#define NH 16
#define KVH 8
#define HD 128
#define MM (BB * SS)          // 4096 rows
#define QKV_N 4096            // q(2048) | k(1024) | v(1024)
#define K3 6144               // 3 * 2048 split-K

// ---------------------------------------------------------------------------
// scratch (device globals — no allocation allowed)
// ---------------------------------------------------------------------------
__device__ __nv_bfloat16 g_xs[MM * K3];       // split x   [M, 3K]
__device__ __nv_bfloat16 g_atts[MM * K3];     // split att [M, 3K] (attn epilogue writes)
__device__ __nv_bfloat16 g_wt[QKV_N * K3];    // Wqkv^T split [4096, 3K]
__device__ __nv_bfloat16 g_wot[DIM * K3];     // Wo^T split   [2048, 3K]
__device__ float g_qkv[MM * QKV_N];           // [M, 4096] = q|k|v
__device__ __nv_bfloat16 g_qh[BB * NH * SS * HD];   // [B,NH,S,128] hi
__device__ __nv_bfloat16 g_ql[BB * NH * SS * HD];   // lo
__device__ __nv_bfloat16 g_kh[BB * KVH * SS * HD];
__device__ __nv_bfloat16 g_kl[BB * KVH * SS * HD];
__device__ __nv_bfloat16 g_vh[BB * KVH * HD * SS];  // [B,KVH,128,S]  (V^T)
__device__ __nv_bfloat16 g_vl[BB * KVH * HD * SS];
__device__ float g_cos[SS * 64];
__device__ float g_sin[SS * 64];

__device__ __forceinline__ uint32_t smem_to_u32(const void* p) {
    uint32_t a;
    asm("{ .reg .u64 t; cvta.to.shared.u64 t, %1; cvt.u32.u64 %0, t; }" : "=r"(a) : "l"(p));
    return a;
}

__device__ __forceinline__ void split2(float a, float b, uint32_t& hi, uint32_t& lo) {
    __nv_bfloat162 h = __float22bfloat162_rn(make_float2(a, b));
    float2 hf = __bfloat1622float2(h);
    __nv_bfloat162 l = __float22bfloat162_rn(make_float2(a - hf.x, b - hf.y));
    hi = *(uint32_t*)&h;
    lo = *(uint32_t*)&l;
}

// ---------------------------------------------------------------------------
// split A [4096, 2048] fp32 -> [4096, 6144] bf16: cols [0,2K)=hi, [2K,4K)=hi, [4K,6K)=lo
// ---------------------------------------------------------------------------
__global__ __launch_bounds__(256) void split_a_kernel(const float* __restrict__ A,
                                                      __nv_bfloat16* __restrict__ As) {
    int idx = blockIdx.x * 256 + threadIdx.x;
    if (idx >= MM * DIM) return;
    int m = idx >> 11, k = idx & 2047;
    float v = A[idx];
    __nv_bfloat16 h = __float2bfloat16(v);
    __nv_bfloat16 lo = __float2bfloat16(v - __bfloat162float(h));
    size_t rb = (size_t)m * K3 + k;
    As[rb] = h; As[rb + 2048] = h; As[rb + 4096] = lo;
}

// ---------------------------------------------------------------------------
// transpose+split W [2048, N] fp32 -> Wt [N, 6144] bf16: [0,2K)=hi, [2K,4K)=lo, [4K,6K)=hi
// ---------------------------------------------------------------------------
__global__ __launch_bounds__(256) void transpose_split_kernel(const float* __restrict__ W,
                                                              __nv_bfloat16* __restrict__ Wt, int N) {
    __shared__ float tile[32][33];
    int k0 = blockIdx.y * 32, n0 = blockIdx.x * 32;
    int tx = threadIdx.x, ty = threadIdx.y;
#pragma unroll
    for (int i = 0; i < 4; i++)
        tile[ty + i * 8][tx] = W[(size_t)(k0 + ty + i * 8) * N + n0 + tx];
    __syncthreads();
#pragma unroll
    for (int i = 0; i < 4; i++) {
        int n = n0 + ty + i * 8;
        float v = tile[tx][ty + i * 8];
        __nv_bfloat16 h = __float2bfloat16(v);
        __nv_bfloat16 lo = __float2bfloat16(v - __bfloat162float(h));
        size_t rb = (size_t)n * K3 + k0 + tx;
        Wt[rb] = h; Wt[rb + 2048] = lo; Wt[rb + 4096] = h;
    }
}

// ---------------------------------------------------------------------------
// bf16 mma.sync GEMM (validated R4): C[M, Ntot] = A[M, K3] · Bt[Ntot, K3]^T
// ---------------------------------------------------------------------------
#define NSTAGES 3
#define STAGE_ELEMS (128 * 40)
#define GEMM_SMEM (NSTAGES * 2 * STAGE_ELEMS * 2)
#define NKT (K3 / 32)

__global__ __launch_bounds__(256) void gemm_kernel(const __nv_bfloat16* __restrict__ A,
                                                   const __nv_bfloat16* __restrict__ Bt,
                                                   float* __restrict__ C, int Ntot) {
    extern __shared__ __nv_bfloat16 smem[];
    int tid = threadIdx.x;
    int lane = tid & 31;
    int wid = tid >> 5;
    int wm = wid >> 2;
    int wn = wid & 3;

    size_t arow0 = (size_t)blockIdx.y * 128;
    size_t brow0 = (size_t)blockIdx.x * 128;
    const __nv_bfloat16* Ag = A + arow0 * K3;
    const __nv_bfloat16* Bg = Bt + brow0 * K3;

    uint32_t sbase = smem_to_u32(smem);
    const uint32_t boff = NSTAGES * STAGE_ELEMS * 2;

    int lrow = tid >> 2;
    int lch = tid & 3;
    auto load_stage = [&](int kt, int s) {
        uint32_t abase = sbase + s * STAGE_ELEMS * 2;
        uint32_t bbase = sbase + boff + s * STAGE_ELEMS * 2;
        const __nv_bfloat16* ag = Ag + (size_t)kt * 32;
        const __nv_bfloat16* bg = Bg + (size_t)kt * 32;
#pragma unroll
        for (int i = 0; i < 2; i++) {
            int row = lrow + i * 64;
            uint32_t so = row * 80 + lch * 16;
            const void* pa = ag + (size_t)row * K3 + lch * 8;
            asm volatile("cp.async.cg.shared.global [%0], [%1], 16;" :: "r"(abase + so), "l"(pa));
            const void* pb = bg + (size_t)row * K3 + lch * 8;
            asm volatile("cp.async.cg.shared.global [%0], [%1], 16;" :: "r"(bbase + so), "l"(pb));
        }
        asm volatile("cp.async.commit_group;" ::: "memory");
    };

    float acc[4][4][4];
#pragma unroll
    for (int i = 0; i < 4; i++)
#pragma unroll
        for (int j = 0; j < 4; j++)
#pragma unroll
            for (int c = 0; c < 4; c++) acc[i][j][c] = 0.f;

    load_stage(0, 0);
    load_stage(1, 1);

    for (int kt = 0; kt < NKT; kt++) {
        int s = kt % NSTAGES;
        asm volatile("cp.async.wait_group 1;" ::: "memory");
        __syncthreads();

        uint32_t abase = sbase + s * STAGE_ELEMS * 2;
        uint32_t bbase = sbase + boff + s * STAGE_ELEMS * 2;
#pragma unroll
        for (int kk = 0; kk < 2; kk++) {
            uint32_t afr[4][4];
            uint32_t bfr[4][2];
#pragma unroll
            for (int mt = 0; mt < 4; mt++) {
                int row = wm * 64 + mt * 16 + (lane & 15);
                uint32_t addr = abase + row * 80 + kk * 32 + (lane >> 4) * 16;
                asm volatile("ldmatrix.sync.aligned.m8n8.x4.shared.b16 {%0,%1,%2,%3}, [%4];"
                             : "=r"(afr[mt][0]), "=r"(afr[mt][1]), "=r"(afr[mt][2]), "=r"(afr[mt][3])
                             : "r"(addr));
            }
#pragma unroll
            for (int nt = 0; nt < 4; nt++) {
                int nrow = wn * 32 + nt * 8 + (lane & 7);
                uint32_t addr = bbase + nrow * 80 + kk * 32 + ((lane >> 3) & 1) * 16;
                asm volatile("ldmatrix.sync.aligned.m8n8.x2.shared.b16 {%0,%1}, [%2];"
                             : "=r"(bfr[nt][0]), "=r"(bfr[nt][1]) : "r"(addr));
            }
#pragma unroll
            for (int mt = 0; mt < 4; mt++)
#pragma unroll
                for (int nt = 0; nt < 4; nt++) {
                    asm volatile(
                        "mma.sync.aligned.m16n8k16.row.col.f32.bf16.bf16.f32 "
                        "{%0,%1,%2,%3}, {%4,%5,%6,%7}, {%8,%9}, {%0,%1,%2,%3};"
                        : "+f"(acc[mt][nt][0]), "+f"(acc[mt][nt][1]),
                          "+f"(acc[mt][nt][2]), "+f"(acc[mt][nt][3])
                        : "r"(afr[mt][0]), "r"(afr[mt][1]), "r"(afr[mt][2]), "r"(afr[mt][3]),
                          "r"(bfr[nt][0]), "r"(bfr[nt][1]));
                }
        }
        __syncthreads();
        if (kt + 2 < NKT) load_stage(kt + 2, (kt + 2) % NSTAGES);
        else asm volatile("cp.async.commit_group;" ::: "memory");
    }

    int r0 = lane >> 2;
    int c0 = (lane & 3) * 2;
#pragma unroll
    for (int mt = 0; mt < 4; mt++) {
        size_t m = arow0 + wm * 64 + mt * 16 + r0;
#pragma unroll
        for (int nt = 0; nt < 4; nt++) {
            size_t n = brow0 + wn * 32 + nt * 8 + c0;
            float2 v0 = make_float2(acc[mt][nt][0], acc[mt][nt][1]);
            float2 v1 = make_float2(acc[mt][nt][2], acc[mt][nt][3]);
            *(float2*)(C + m * Ntot + n) = v0;
            *(float2*)(C + (m + 8) * Ntot + n) = v1;
        }
    }
}

// ---------------------------------------------------------------------------
// RoPE tables (fp64 for accuracy)
// ---------------------------------------------------------------------------
__global__ void rope_table_kernel() {
    int idx = blockIdx.x * blockDim.x + threadIdx.x;
    if (idx >= SS * 64) return;
    int i = idx & 63;
    int s = idx >> 6;
    double inv = pow(10000.0, -(double)i / 64.0);
    double ang = (double)s * inv;
    g_cos[idx] = (float)cos(ang);
    g_sin[idx] = (float)sin(ang);
}

// ---------------------------------------------------------------------------
// RoPE + convert q,k -> head-major bf16 hi/lo [B,H,S,128]
// ---------------------------------------------------------------------------
__global__ void rope_convert_kernel() {
    int idx = blockIdx.x * blockDim.x + threadIdx.x;
    const int qtotal = MM * NH * 64;
    const int ktotal = MM * KVH * 64;
    if (idx >= qtotal + ktotal) return;
    int coloff, nheads;
    __nv_bfloat16 *oh, *ol;
    if (idx < qtotal) { coloff = 0; nheads = NH; oh = g_qh; ol = g_ql; }
    else { coloff = 2048; nheads = KVH; oh = g_kh; ol = g_kl; idx -= qtotal; }
    int i = idx & 63;
    int h = (idx >> 6) % nheads;
    int rs = idx / (64 * nheads);   // b*SS + s
    int s = rs & (SS - 1);
    int b = rs >> 11;
    float c = g_cos[s * 64 + i];
    float sn = g_sin[s * 64 + i];
    const float* p = g_qkv + (size_t)rs * QKV_N + coloff + h * HD;
    float x0 = p[i];
    float x1 = p[i + 64];
    float y0 = x0 * c - x1 * sn;
    float y1 = x1 * c + x0 * sn;
    size_t base = ((size_t)(b * nheads + h) * SS + s) * HD;
    __nv_bfloat16 h0 = __float2bfloat16(y0);
    __nv_bfloat16 h1 = __float2bfloat16(y1);
    oh[base + i] = h0;
    oh[base + i + 64] = h1;
    ol[base + i] = __float2bfloat16(y0 - __bfloat162float(h0));
    ol[base + i + 64] = __float2bfloat16(y1 - __bfloat162float(h1));
}

// ---------------------------------------------------------------------------
// convert v -> transposed bf16 hi/lo [B,KVH,128,S]
// grid (SS/32, 128/32, BB*KVH), block (32,8)
// ---------------------------------------------------------------------------
__global__ void convert_v_kernel() {
    __shared__ float t[32][33];
    int j0 = blockIdx.x * 32, d0 = blockIdx.y * 32;
    int bh = blockIdx.z;
    int b = bh / KVH, hk = bh % KVH;
    int tx = threadIdx.x, ty = threadIdx.y;
#pragma unroll
    for (int i = 0; i < 4; i++) {
        int j = j0 + ty + i * 8;
        t[ty + i * 8][tx] = g_qkv[(size_t)(b * SS + j) * QKV_N + 3072 + hk * HD + d0 + tx];
    }
    __syncthreads();
#pragma unroll
    for (int i = 0; i < 4; i++) {
        int d = d0 + ty + i * 8;
        int j = j0 + tx;
        float v = t[tx][ty + i * 8];
        size_t dst = ((size_t)(b * KVH + hk) * HD + d) * SS + j;
        __nv_bfloat16 h = __float2bfloat16(v);
        g_vh[dst] = h;
        g_vl[dst] = __float2bfloat16(v - __bfloat162float(h));
    }
}

// ---------------------------------------------------------------------------
// Tensor-core causal GQA flash attention.
// Grid (32, NH, BB), 128 threads (4 warps, warp w = q rows [w*16, w*16+16)).
// Tile 64q x 64k. hi/lo split: S = qh·kh + ql·kh + qh·kl; O += ph·vh + pl·vh + ph·vl.
// Epilogue writes g_atts [M,K3] (hi|hi|lo) directly.
// ---------------------------------------------------------------------------
#define AQ_STR 136      // Q/K smem row stride (bf16 elems) -> 272B, conflict-free
#define AV_STR 72       // V^T row stride -> 144B
#define O_QH 0
#define O_QL (64 * AQ_STR)
#define O_KH (2 * 64 * AQ_STR)
#define O_KL (3 * 64 * AQ_STR)
#define O_VH (4 * 64 * AQ_STR)
#define O_VL (4 * 64 * AQ_STR + 128 * AV_STR)
#define ATTN_SMEM ((4 * 64 * AQ_STR + 2 * 128 * AV_STR) * 2)

__global__ __launch_bounds__(128) void attn_kernel() {
    extern __shared__ __nv_bfloat16 asmem[];
    int qt = blockIdx.x;
    int h = blockIdx.y;
    int b = blockIdx.z;
    int hk = h >> 1;
    int tid = threadIdx.x;
    int lane = tid & 31;
    int w = tid >> 5;
    uint32_t sb = smem_to_u32(asmem);
    const float scale = 0.08838834764831845f;

    // load Q tile (hi & lo): rows qt*64..+63
    {
        const __nv_bfloat16* qh_g = g_qh + ((size_t)(b * NH + h) * SS + qt * 64) * HD;
        const __nv_bfloat16* ql_g = g_ql + ((size_t)(b * NH + h) * SS + qt * 64) * HD;
        for (int i = tid; i < 1024; i += 128) {
            int row = i >> 4, c = i & 15;
            *(uint4*)&asmem[O_QH + row * AQ_STR + c * 8] = *(const uint4*)(qh_g + row * HD + c * 8);
            *(uint4*)&asmem[O_QL + row * AQ_STR + c * 8] = *(const uint4*)(ql_g + row * HD + c * 8);
        }
    }

    float o[16][4];
#pragma unroll
    for (int i = 0; i < 16; i++)
#pragma unroll
        for (int c = 0; c < 4; c++) o[i][c] = 0.f;
    float m0 = -1e30f, m1 = -1e30f, l0 = 0.f, l1 = 0.f;

    const __nv_bfloat16* kh_g0 = g_kh + ((size_t)(b * KVH + hk) * SS) * HD;
    const __nv_bfloat16* kl_g0 = g_kl + ((size_t)(b * KVH + hk) * SS) * HD;
    const __nv_bfloat16* vh_g0 = g_vh + (size_t)(b * KVH + hk) * HD * SS;
    const __nv_bfloat16* vl_g0 = g_vl + (size_t)(b * KVH + hk) * HD * SS;

    int rl0 = w * 16 + (lane >> 2);      // local q row for c0,c1 (c2,c3 -> +8)
    int cl = (lane & 3) * 2;

    for (int jt = 0; jt <= qt; jt++) {
        __syncthreads();   // prev iter done with K/V smem
        // cp.async K (64x128) and V^T (128x64) hi/lo
        const __nv_bfloat16* kh_g = kh_g0 + (size_t)jt * 64 * HD;
        const __nv_bfloat16* kl_g = kl_g0 + (size_t)jt * 64 * HD;
        const __nv_bfloat16* vh_g = vh_g0 + jt * 64;
        const __nv_bfloat16* vl_g = vl_g0 + jt * 64;
#pragma unroll
        for (int i = 0; i < 8; i++) {
            int idx = tid + i * 128;
            int row = idx >> 4, c = idx & 15;
            uint32_t so = sb + (O_KH + row * AQ_STR + c * 8) * 2;
            asm volatile("cp.async.cg.shared.global [%0], [%1], 16;"
                         :: "r"(so), "l"(kh_g + row * HD + c * 8));
            so = sb + (O_KL + row * AQ_STR + c * 8) * 2;
            asm volatile("cp.async.cg.shared.global [%0], [%1], 16;"
                         :: "r"(so), "l"(kl_g + row * HD + c * 8));
            int vrow = idx >> 3, vc = idx & 7;
            so = sb + (O_VH + vrow * AV_STR + vc * 8) * 2;
            asm volatile("cp.async.cg.shared.global [%0], [%1], 16;"
                         :: "r"(so), "l"(vh_g + (size_t)vrow * SS + vc * 8));
            so = sb + (O_VL + vrow * AV_STR + vc * 8) * 2;
            asm volatile("cp.async.cg.shared.global [%0], [%1], 16;"
                         :: "r"(so), "l"(vl_g + (size_t)vrow * SS + vc * 8));
        }
        asm volatile("cp.async.commit_group;" ::: "memory");
        asm volatile("cp.async.wait_group 0;" ::: "memory");
        __syncthreads();

        // ---- scores: S = qh·kh + ql·kh + qh·kl ----
        float sacc[8][4];
#pragma unroll
        for (int nf = 0; nf < 8; nf++)
#pragma unroll
            for (int c = 0; c < 4; c++) sacc[nf][c] = 0.f;

#pragma unroll
        for (int kk = 0; kk < 8; kk++) {
            uint32_t qhf[4], qlf[4];
            uint32_t aaddr = sb + (O_QH + (w * 16 + (lane & 15)) * AQ_STR + kk * 16 + (lane >> 4) * 8) * 2;
            asm volatile("ldmatrix.sync.aligned.m8n8.x4.shared.b16 {%0,%1,%2,%3}, [%4];"
                         : "=r"(qhf[0]), "=r"(qhf[1]), "=r"(qhf[2]), "=r"(qhf[3]) : "r"(aaddr));
            aaddr = sb + (O_QL + (w * 16 + (lane & 15)) * AQ_STR + kk * 16 + (lane >> 4) * 8) * 2;
            asm volatile("ldmatrix.sync.aligned.m8n8.x4.shared.b16 {%0,%1,%2,%3}, [%4];"
                         : "=r"(qlf[0]), "=r"(qlf[1]), "=r"(qlf[2]), "=r"(qlf[3]) : "r"(aaddr));
#pragma unroll
            for (int nf = 0; nf < 8; nf++) {
                uint32_t khf[2], klf[2];
                uint32_t baddr = sb + (O_KH + (nf * 8 + (lane & 7)) * AQ_STR + kk * 16 + ((lane >> 3) & 1) * 8) * 2;
                asm volatile("ldmatrix.sync.aligned.m8n8.x2.shared.b16 {%0,%1}, [%2];"
                             : "=r"(khf[0]), "=r"(khf[1]) : "r"(baddr));
                baddr = sb + (O_KL + (nf * 8 + (lane & 7)) * AQ_STR + kk * 16 + ((lane >> 3) & 1) * 8) * 2;
                asm volatile("ldmatrix.sync.aligned.m8n8.x2.shared.b16 {%0,%1}, [%2];"
                             : "=r"(klf[0]), "=r"(klf[1]) : "r"(baddr));
#define MMA_S(af, bf) \
    asm volatile("mma.sync.aligned.m16n8k16.row.col.f32.bf16.bf16.f32 " \
                 "{%0,%1,%2,%3}, {%4,%5,%6,%7}, {%8,%9}, {%0,%1,%2,%3};" \
                 : "+f"(sacc[nf][0]), "+f"(sacc[nf][1]), "+f"(sacc[nf][2]), "+f"(sacc[nf][3]) \
                 : "r"((af)[0]), "r"((af)[1]), "r"((af)[2]), "r"((af)[3]), "r"((bf)[0]), "r"((bf)[1]))
                MMA_S(qhf, khf);
                MMA_S(qlf, khf);
                MMA_S(qhf, klf);
            }
        }

        // ---- masking + online softmax ----
        bool diag = (jt == qt);
        float mt0 = -1e30f, mt1 = -1e30f;
#pragma unroll
        for (int nf = 0; nf < 8; nf++) {
            int c0i = nf * 8 + cl;
            float s0 = sacc[nf][0] * scale;
            float s1 = sacc[nf][1] * scale;
            float s2 = sacc[nf][2] * scale;
            float s3 = sacc[nf][3] * scale;
            if (diag) {
                if (c0i > rl0) s0 = -1e30f;
                if (c0i + 1 > rl0) s1 = -1e30f;
                if (c0i > rl0 + 8) s2 = -1e30f;
                if (c0i + 1 > rl0 + 8) s3 = -1e30f;
            }
            sacc[nf][0] = s0; sacc[nf][1] = s1; sacc[nf][2] = s2; sacc[nf][3] = s3;
            mt0 = fmaxf(mt0, fmaxf(s0, s1));
            mt1 = fmaxf(mt1, fmaxf(s2, s3));
        }
        mt0 = fmaxf(mt0, __shfl_xor_sync(0xffffffff, mt0, 1));
        mt0 = fmaxf(mt0, __shfl_xor_sync(0xffffffff, mt0, 2));
        mt1 = fmaxf(mt1, __shfl_xor_sync(0xffffffff, mt1, 1));
        mt1 = fmaxf(mt1, __shfl_xor_sync(0xffffffff, mt1, 2));
        float mn0 = fmaxf(m0, mt0), mn1 = fmaxf(m1, mt1);
        float a0 = __expf(m0 - mn0), a1 = __expf(m1 - mn1);
        m0 = mn0; m1 = mn1;

        uint32_t ph[4][4], pl[4][4];
        float ls0 = 0.f, ls1 = 0.f;
#pragma unroll
        for (int nf = 0; nf < 8; nf++) {
            float p0 = __expf(sacc[nf][0] - mn0);
            float p1 = __expf(sacc[nf][1] - mn0);
            float p2 = __expf(sacc[nf][2] - mn1);
            float p3 = __expf(sacc[nf][3] - mn1);
            ls0 += p0 + p1;
            ls1 += p2 + p3;
            int kkp = nf >> 1, off = (nf & 1) * 2;
            split2(p0, p1, ph[kkp][off], pl[kkp][off]);
            split2(p2, p3, ph[kkp][off + 1], pl[kkp][off + 1]);
        }
        ls0 += __shfl_xor_sync(0xffffffff, ls0, 1);
        ls0 += __shfl_xor_sync(0xffffffff, ls0, 2);
        ls1 += __shfl_xor_sync(0xffffffff, ls1, 1);
        ls1 += __shfl_xor_sync(0xffffffff, ls1, 2);
        l0 = l0 * a0 + ls0;
        l1 = l1 * a1 + ls1;

        // rescale O
#pragma unroll
        for (int nf2 = 0; nf2 < 16; nf2++) {
            o[nf2][0] *= a0; o[nf2][1] *= a0;
            o[nf2][2] *= a1; o[nf2][3] *= a1;
        }

        // ---- O += ph·vh + pl·vh + ph·vl ----
#pragma unroll
        for (int nf2 = 0; nf2 < 16; nf2++) {
#pragma unroll
            for (int kkp = 0; kkp < 4; kkp++) {
                uint32_t vhf[2], vlf[2];
                uint32_t baddr = sb + (O_VH + (nf2 * 8 + (lane & 7)) * AV_STR + kkp * 16 + ((lane >> 3) & 1) * 8) * 2;
                asm volatile("ldmatrix.sync.aligned.m8n8.x2.shared.b16 {%0,%1}, [%2];"
                             : "=r"(vhf[0]), "=r"(vhf[1]) : "r"(baddr));
                baddr = sb + (O_VL + (nf2 * 8 + (lane & 7)) * AV_STR + kkp * 16 + ((lane >> 3) & 1) * 8) * 2;
                asm volatile("ldmatrix.sync.aligned.m8n8.x2.shared.b16 {%0,%1}, [%2];"
                             : "=r"(vlf[0]), "=r"(vlf[1]) : "r"(baddr));
#define MMA_O(af, bf) \
    asm volatile("mma.sync.aligned.m16n8k16.row.col.f32.bf16.bf16.f32 " \
                 "{%0,%1,%2,%3}, {%4,%5,%6,%7}, {%8,%9}, {%0,%1,%2,%3};" \
                 : "+f"(o[nf2][0]), "+f"(o[nf2][1]), "+f"(o[nf2][2]), "+f"(o[nf2][3]) \
                 : "r"((af)[0]), "r"((af)[1]), "r"((af)[2]), "r"((af)[3]), "r"((bf)[0]), "r"((bf)[1]))
                MMA_O(ph[kkp], vhf);
                MMA_O(pl[kkp], vhf);
                MMA_O(ph[kkp], vlf);
            }
        }
    }

    // epilogue -> g_atts [M, K3]: hi at k, hi at k+2048, lo at k+4096
    float inv0 = 1.f / l0, inv1 = 1.f / l1;
    size_t row0g = (size_t)b * SS + qt * 64 + w * 16 + (lane >> 2);
    size_t row1g = row0g + 8;
#pragma unroll
    for (int nf2 = 0; nf2 < 16; nf2++) {
        int d = h * HD + nf2 * 8 + cl;
        uint32_t hi, lo;
        split2(o[nf2][0] * inv0, o[nf2][1] * inv0, hi, lo);
        __nv_bfloat16* p0 = g_atts + row0g * K3 + d;
        *(uint32_t*)(p0) = hi; *(uint32_t*)(p0 + 2048) = hi; *(uint32_t*)(p0 + 4096) = lo;
        split2(o[nf2][2] * inv1, o[nf2][3] * inv1, hi, lo);
        __nv_bfloat16* p1 = g_atts + row1g * K3 + d;
        *(uint32_t*)(p1) = hi; *(uint32_t*)(p1 + 2048) = hi; *(uint32_t*)(p1 + 4096) = lo;
    }
}

// ---------------------------------------------------------------------------

extern "C" void kernel_launch(void* const* d_in, const int* in_sizes, int n_in,
                              void* d_out, int out_size) {
    const float* x  = (const float*)d_in[0];
    const float* Wq = (const float*)d_in[1];
    const float* Wk = (const float*)d_in[2];
    const float* Wv = (const float*)d_in[3];
    const float* Wo = (const float*)d_in[4];
    float* out = (float*)d_out;

    __nv_bfloat16 *xs, *atts, *wt, *wot;
    float* qkv;
    cudaGetSymbolAddress((void**)&xs, g_xs);
    cudaGetSymbolAddress((void**)&atts, g_atts);
    cudaGetSymbolAddress((void**)&wt, g_wt);
    cudaGetSymbolAddress((void**)&wot, g_wot);
    cudaGetSymbolAddress((void**)&qkv, g_qkv);

    cudaFuncSetAttribute(attn_kernel, cudaFuncAttributeMaxDynamicSharedMemorySize, ATTN_SMEM);
    cudaFuncSetAttribute(gemm_kernel, cudaFuncAttributeMaxDynamicSharedMemorySize, GEMM_SMEM);

    // prep: split x, transpose+split weights
    split_a_kernel<<<(MM * DIM) / 256, 256>>>(x, xs);
    transpose_split_kernel<<<dim3(2048 / 32, 64), dim3(32, 8)>>>(Wq, wt, 2048);
    transpose_split_kernel<<<dim3(1024 / 32, 64), dim3(32, 8)>>>(Wk, wt + (size_t)2048 * K3, 1024);
    transpose_split_kernel<<<dim3(1024 / 32, 64), dim3(32, 8)>>>(Wv, wt + (size_t)3072 * K3, 1024);
    transpose_split_kernel<<<dim3(2048 / 32, 64), dim3(32, 8)>>>(Wo, wot, 2048);

    // fused QKV projection
    gemm_kernel<<<dim3(QKV_N / 128, MM / 128), 256, GEMM_SMEM>>>(xs, wt, qkv, QKV_N);

    // RoPE + convert to attention layouts
    rope_table_kernel<<<(SS * 64 + 255) / 256, 256>>>();
    rope_convert_kernel<<<(MM * (NH + KVH) * 64 + 255) / 256, 256>>>();
    convert_v_kernel<<<dim3(SS / 32, HD / 32, BB * KVH), dim3(32, 8)>>>();

    // tensor-core flash attention (writes g_atts pre-split)
    attn_kernel<<<dim3(SS / 64, NH, BB), 128, ATTN_SMEM>>>();

    // output projection
    gemm_kernel<<<dim3(DIM / 128, MM / 128), 256, GEMM_SMEM>>>(atts, wot, out, DIM);
}